// round 13
// baseline (speedup 1.0000x reference)
#include <cuda_runtime.h>
#include <math.h>

// ---------------- problem constants ----------------
#define NB 8
#define NA 3
#define GS 128
#define NC (NA*5)
#define NPRED (NA*GS*GS)          // 49152 preds per image
#define NTOT  (NB*NPRED)          // 393216
#define MG 64                     // number of gt rows
#define MASKW (NPRED/32)          // 1536 words
#define NSUM 9
#define NPART (NTOT/1024)         // 384 loss blocks (one pred per thread, 1024/block)
#define SEGK (NPRED/1024)         // 48 elements per thread segment

// ---------------- scratch (static device memory; no allocations) ----------------
__device__ float4       g_box [NTOT];    // (cx,cy,w,h)
__device__ float        g_conf[NTOT];    // clipped conf
__device__ unsigned int g_mt  [NTOT];    // 0 = unmatched; 0x80000000|j = matched to gt j
__device__ float        g_topv[MG*MG];
__device__ int          g_topi[MG*MG];
__device__ float        g_part[NSUM*NPART];   // [q][block] transposed
__device__ int          g_ctr2;          // loss completion ticket (reset by consumer)

// ---------------- helpers ----------------
__device__ __forceinline__ void giou_pair(
    float px1, float py1, float px2, float py2,
    float gx1, float gy1, float gx2, float gy2,
    float& iou, float& gou)
{
    float iw = fminf(px2, gx2) - fmaxf(px1, gx1); iw = fmaxf(iw, 0.f);
    float ih = fminf(py2, gy2) - fmaxf(py1, gy1); ih = fmaxf(ih, 0.f);
    float inter = iw * ih;
    float ap = (px2 - px1) * (py2 - py1);
    float ag = (gx2 - gx1) * (gy2 - gy1);
    float un = ap + ag - inter;
    iou = __fdividef(inter, un + 1e-16f);
    float cw = fmaxf(px2, gx2) - fminf(px1, gx1);
    float ch = fmaxf(py2, gy2) - fminf(py1, gy1);
    float ac = cw * ch;
    gou = iou - __fdividef(ac - un, ac + 1e-16f);
}

// ---------------- 1. pred transform (+ scratch init) ----------------
__global__ void k_pred(const float* __restrict__ out)
{
    int t = blockIdx.x * blockDim.x + threadIdx.x;       // < NTOT
    int x = t & (GS - 1);
    int y = (t >> 7) & (GS - 1);
    int a = (t / (GS * GS)) % NA;
    int b = t / NPRED;
    const float* base = out + (((size_t)b * NC + a * 5) * GS + y) * GS + x;
    float p0 = base[0];
    float p1 = base[GS * GS];
    float p2 = base[2 * GS * GS];
    float p3 = base[3 * GS * GS];
    float p4 = base[4 * GS * GS];
    float xs = (tanhf(p0) + 0.5f + (float)x) / (float)GS;
    float ys = (tanhf(p1) + 0.5f + (float)y) / (float)GS;
    float ws = expf(-p2 * p2);
    float hs = expf(-p3 * p3);
    float c  = 1.f / (1.f + expf(-p4));
    float cc = fminf(fmaxf(c, 1e-7f), 1.f - 1e-7f);
    g_box [t] = make_float4(xs, ys, ws, hs);
    g_conf[t] = cc;
    g_mt  [t] = 0u;
}

// ---------------- 2. per-gt top-m lists (no atomics) ----------------
__global__ void k_topk(const float* __restrict__ gts)
{
    extern __shared__ float dyn[];
    float* row  = dyn;                          // [NPRED]
    float* segv = dyn + NPRED;                  // [1024]
    int*   segi = (int*)(dyn + NPRED + 1024);   // [1024]
    __shared__ float swv[32];
    __shared__ int   swi[32];
    __shared__ int   bbi;
    __shared__ int   smm;

    int j = blockIdx.x;
    int tid = threadIdx.x;              // 1024
    int b = (int)__ldg(&gts[j * 5]);

    if (tid == 0) {
        int m = 0;
        for (int i = 0; i < MG; i++)
            if ((int)__ldg(&gts[i * 5]) == b) m++;
        smm = m;
    }

    float cx = __ldg(&gts[j * 5 + 1]), cy = __ldg(&gts[j * 5 + 2]);
    float w  = __ldg(&gts[j * 5 + 3]), h  = __ldg(&gts[j * 5 + 4]);
    float gx1 = cx - w * 0.5f, gx2 = cx + w * 0.5f;
    float gy1 = cy - h * 0.5f, gy2 = cy + h * 0.5f;
    const float4* bx = &g_box[(size_t)b * NPRED];

    // initial pass: giou, fill smem row, per-thread segment max
    float bv = -1e30f; int bi = NPRED;
#pragma unroll 8
    for (int k = 0; k < SEGK; k++) {
        int p = tid + k * 1024;
        float4 B = __ldg(&bx[p]);
        float px1 = B.x - B.z * 0.5f, px2 = B.x + B.z * 0.5f;
        float py1 = B.y - B.w * 0.5f, py2 = B.y + B.w * 0.5f;
        float iou, gou;
        giou_pair(px1, py1, px2, py2, gx1, gy1, gx2, gy2, iou, gou);
        row[p] = gou;
        if (gou > bv) { bv = gou; bi = p; }      // ascending p keeps min idx on ties
    }
    segv[tid] = bv; segi[tid] = bi;
    unsigned long long pk = 0ull;                // picked bits within my segment
    __syncthreads();
    int m = smm;

    for (int r = 0; r < m; r++) {
        // block argmax over 1024 segment maxima (min-global-index tie-break)
        float v = segv[tid]; int i = segi[tid];
#pragma unroll
        for (int o = 16; o > 0; o >>= 1) {
            float ov = __shfl_down_sync(0xffffffffu, v, o);
            int   oi = __shfl_down_sync(0xffffffffu, i, o);
            if (ov > v || (ov == v && oi < i)) { v = ov; i = oi; }
        }
        if ((tid & 31) == 0) { swv[tid >> 5] = v; swi[tid >> 5] = i; }
        __syncthreads();
        if (tid < 32) {
            v = swv[tid]; i = swi[tid];
#pragma unroll
            for (int o = 16; o > 0; o >>= 1) {
                float ov = __shfl_down_sync(0xffffffffu, v, o);
                int   oi = __shfl_down_sync(0xffffffffu, i, o);
                if (ov > v || (ov == v && oi < i)) { v = ov; i = oi; }
            }
            if (tid == 0) {
                bbi = i;
                g_topv[j * MG + r] = v;
                g_topi[j * MG + r] = i;
            }
        }
        __syncthreads();
        int wi = bbi;
        if (tid == (wi & 1023)) {
            pk |= 1ull << (wi >> 10);
            float nv = -1e30f; int ni = NPRED;
#pragma unroll
            for (int k = 0; k < SEGK; k++) {
                if ((pk >> k) & 1ull) continue;
                int p = tid + k * 1024;
                float vv = row[p];
                if (vv > nv) { nv = vv; ni = p; }
            }
            segv[tid] = nv; segi[tid] = ni;
        }
        // no barrier: only the rescanner's own segv entry changed and only
        // that thread reads it next round.
    }
}

// ---------------- 3. greedy matcher; flags matched preds in g_mt ----------------
__global__ void k_match(const float* __restrict__ gts)
{
    int b = blockIdx.x;
    __shared__ unsigned int mk[MASKW];          // 6 KB
    __shared__ float stv[MG * MG];              // 16 KB
    __shared__ int   sti[MG * MG];              // 16 KB
    __shared__ int   sgb[MG];
    int tid = threadIdx.x;                      // 512

    for (int i = tid; i < MASKW; i += 512) mk[i] = 0u;
    for (int i = tid; i < MG * MG; i += 512) { stv[i] = g_topv[i]; sti[i] = g_topi[i]; }
    if (tid < MG) sgb[tid] = (int)gts[tid * 5];
    __syncthreads();
    if (tid != 0) return;

    int jl[MG]; int mc = 0;
    for (int j = 0; j < MG; j++) if (sgb[j] == b) jl[mc++] = j;
    int m = mc;
    if (m == 0) return;
    bool sel[MG];
    for (int i = 0; i < mc; i++) sel[i] = false;
    float valj[MG]; int pdj[MG]; int act[MG];

    while (true) {
        int ma = 0;
        for (int i = 0; i < mc; i++) if (!sel[i]) act[ma++] = i;
        if (ma == 0) break;
        for (int ii = 0; ii < ma; ii++) {
            int j = jl[act[ii]];
            valj[ii] = stv[j * MG + m - 1];
            pdj[ii]  = sti[j * MG + m - 1];
            for (int r = 0; r < m; r++) {
                int p = sti[j * MG + r];
                if (!((mk[p >> 5] >> (p & 31)) & 1u)) {
                    valj[ii] = stv[j * MG + r];
                    pdj[ii] = p;
                    break;
                }
            }
        }
        for (int ii = 0; ii < ma; ii++) {
            int p = pdj[ii];
            bool first = true;
            for (int k = 0; k < ii; k++) if (pdj[k] == p) { first = false; break; }
            if (!first) continue;
            float mx = valj[ii];
            for (int k = ii + 1; k < ma; k++)
                if (pdj[k] == p && valj[k] > mx) mx = valj[k];
            int win = ii;
            for (int k = ii; k < ma; k++)
                if (pdj[k] == p && valj[k] >= mx) { win = k; break; }
            sel[act[win]] = true;
            mk[p >> 5] |= 1u << (p & 31);
            g_mt[(size_t)b * NPRED + p] = 0x80000000u | (unsigned int)jl[act[win]];
        }
    }
}

// ---------------- 4. loss: 1024-thread blocks, one pred per thread, mc-loop default ----------------
__global__ void k_loss(const float* __restrict__ gts, float* __restrict__ outv)
{
    __shared__ float sgt[MG * 5];          // raw gts
    __shared__ float slw[MG], slh[MG];     // per-gt log(w), log(h)
    __shared__ float cx1[MG], cy1[MG], cx2[MG], cy2[MG];  // compacted corners
    __shared__ int   cj[MG];
    __shared__ int   smc;
    __shared__ int   slast;
    __shared__ float red[32 * NSUM];
    int tid = threadIdx.x;                 // 1024
    int b = blockIdx.x / (NPRED / 1024);   // 48 blocks per image
    for (int i = tid; i < MG * 5; i += 1024) sgt[i] = gts[i];
    __syncthreads();
    if (tid < MG) {
        slw[tid] = logf(sgt[tid * 5 + 3]);
        slh[tid] = logf(sgt[tid * 5 + 4]);
    }
    if (tid == 0) {
        int mc = 0;
        for (int j = 0; j < MG; j++) {
            if ((int)sgt[j * 5] != b) continue;
            float gcx = sgt[j * 5 + 1], gcy = sgt[j * 5 + 2];
            float gw  = sgt[j * 5 + 3], gh  = sgt[j * 5 + 4];
            cx1[mc] = gcx - gw * 0.5f; cx2[mc] = gcx + gw * 0.5f;
            cy1[mc] = gcy - gh * 0.5f; cy2[mc] = gcy + gh * 0.5f;
            cj[mc] = j;
            mc++;
        }
        smc = mc;
    }
    __syncthreads();
    int mc = smc;

    int t = blockIdx.x * 1024 + tid;
    // three independent loads, issued together
    float4 B = __ldg(&g_box[t]);
    unsigned int mt = __ldg(&g_mt[t]);
    float cc = __ldg(&g_conf[t]);

    bool tp = (mt & 0x80000000u) != 0u;
    float tpf = tp ? 1.f : 0.f;
    int pi = 0;
    float iou = 0.f, gou = 0.f;

    float px1 = B.x - B.z * 0.5f, px2 = B.x + B.z * 0.5f;
    float py1 = B.y - B.w * 0.5f, py2 = B.y + B.w * 0.5f;

    if (tp) {
        pi = (int)(mt & 0x7FFFFFFFu);
        float tx = sgt[pi * 5 + 1], ty = sgt[pi * 5 + 2];
        float tw = sgt[pi * 5 + 3], th = sgt[pi * 5 + 4];
        giou_pair(px1, py1, px2, py2,
                  tx - tw * 0.5f, ty - th * 0.5f,
                  tx + tw * 0.5f, ty + th * 0.5f, iou, gou);
    } else if (mc > 0) {
        // default: best gt of this image by giou (ascending -> first-index tie-break)
        float best = -1e30f; int bi = 0; float biou = 0.f;
        for (int k = 0; k < mc; k++) {
            float ji, jg;
            giou_pair(px1, py1, px2, py2, cx1[k], cy1[k], cx2[k], cy2[k], ji, jg);
            if (jg > best) { best = jg; bi = k; biou = ji; }
        }
        iou = biou; gou = best;
        pi = cj[bi];
    }
    // mc==0: iou=gou=0, pi=0 (matches reference)

    float tx = sgt[pi * 5 + 1], ty = sgt[pi * 5 + 2];
    float lwgt = slw[pi], lhgt = slh[pi];

    bool thr = iou > 0.5f;
    float igf = ((!thr) || tp) ? 1.f : 0.f;
    float bce = tp ? -logf(cc) : -log1pf(-cc);

    float s[NSUM];
    s[0] = tpf;
    float dx = B.x - tx, dy = B.y - ty;
    s[1] = (dx * dx + dy * dy) * tpf;
    float dw = logf(B.z) - lwgt, dh = logf(B.w) - lhgt;
    s[2] = (dw * dw + dh * dh) * tpf;
    s[3] = gou * tpf;
    s[4] = iou * tpf;
    s[5] = igf;
    s[6] = bce * igf;
    s[7] = cc * tpf;
    s[8] = cc * cc * igf;

#pragma unroll
    for (int o = 16; o > 0; o >>= 1) {
#pragma unroll
        for (int q = 0; q < NSUM; q++)
            s[q] += __shfl_down_sync(0xffffffffu, s[q], o);
    }
    if ((tid & 31) == 0) {
#pragma unroll
        for (int q = 0; q < NSUM; q++) red[(tid >> 5) * NSUM + q] = s[q];
    }
    __syncthreads();
    if (tid < NSUM) {
        float acc = 0.f;
        for (int w = 0; w < 32; w++) acc += red[w * NSUM + tid];
        g_part[tid * NPART + blockIdx.x] = acc;     // transposed: contiguous per q
    }

    // ---- completion ticket: last block folds and writes the output ----
    __threadfence();
    __syncthreads();
    if (tid == 0) {
        int done = atomicAdd(&g_ctr2, 1);
        slast = (done == NPART - 1);
        if (slast) g_ctr2 = 0;              // reset for next replay
    }
    __syncthreads();
    if (!slast) return;
    __threadfence();

    // parallel fold: 16 threads per sum, width-16 shuffle.
    // ALL threads execute the shuffle (a=0 for out-of-range lanes) — guards
    // only on accumulation and the final store, so no intra-warp divergence.
    __shared__ double S[NSUM];
    {
        int q = tid >> 4;
        int sub = tid & 15;
        double a = 0.0;
        if (q < NSUM) {
            const float* p = &g_part[q * NPART];
            for (int i = sub; i < NPART; i += 16) a += (double)p[i];
        }
#pragma unroll
        for (int o = 8; o > 0; o >>= 1)
            a += __shfl_down_sync(0xffffffffu, a, o, 16);
        if (q < NSUM && sub == 0) S[q] = a;
    }
    __syncthreads();
    if (tid == 0) {
        float s0 = (float)S[0], s1 = (float)S[1], s2 = (float)S[2];
        float s3 = (float)S[3], s4 = (float)S[4], s5 = (float)S[5];
        float s6 = (float)S[6], s7 = (float)S[7], s8 = (float)S[8];
        float cnt = fmaxf(s0, 1.f);
        float lxy  = s1 / cnt;
        float lwh  = s2 / cnt;
        float lgou = 1.f - s3 / cnt;
        float liou = 1.f - s4 / cnt;
        float icnt = fmaxf(s5, 1.f);
        float lbce = s6 / icnt;
        float dice = 1.f - (2.f * s7 + 1.f) / (s8 + s0 + 1.f);
        float lconf = dice + lbce;
        float tot = lconf + 2.f * lgou + lwh + lxy;
        outv[0] = lxy; outv[1] = lwh; outv[2] = lconf;
        outv[3] = liou; outv[4] = lgou; outv[5] = tot;
    }
}

// ---------------- launch ----------------
extern "C" void kernel_launch(void* const* d_in, const int* in_sizes, int n_in,
                              void* d_out, int out_size)
{
    const float* out = (const float*)d_in[0];   // [8,15,128,128]
    const float* gts = (const float*)d_in[1];   // [64,5]
    float* res = (float*)d_out;                 // [6]

    static int smem_set = 0;
    const int TOPK_SMEM = (NPRED + 1024 + 1024) * 4 + 64;   // ~204.9 KB
    if (!smem_set) {
        cudaFuncSetAttribute(k_topk, cudaFuncAttributeMaxDynamicSharedMemorySize, TOPK_SMEM);
        smem_set = 1;
    }

    k_pred  <<<NTOT / 512, 512>>>(out);
    k_topk  <<<MG, 1024, TOPK_SMEM>>>(gts);
    k_match <<<NB, 512>>>(gts);
    k_loss  <<<NPART, 1024>>>(gts, res);
}

// round 14
// speedup vs baseline: 1.2026x; 1.2026x over previous
#include <cuda_runtime.h>
#include <math.h>

// ---------------- problem constants ----------------
#define NB 8
#define NA 3
#define GS 128
#define NC (NA*5)
#define NPRED (NA*GS*GS)          // 49152 preds per image
#define NTOT  (NB*NPRED)          // 393216
#define MG 64                     // number of gt rows
#define MASKW (NPRED/32)          // 1536 words
#define NSUM 9
#define LOSS_CHUNK 1024
#define NPART (NTOT/LOSS_CHUNK)   // 384 loss blocks
#define SEGK (NPRED/1024)         // 48 elements per thread segment

// ---------------- scratch (static device memory; no allocations) ----------------
__device__ float4       g_box [NTOT];    // (cx,cy,w,h)
__device__ float        g_conf[NTOT];    // clipped conf
__device__ unsigned int g_mt  [NTOT];    // 0 = unmatched; 0x80000000|j = matched to gt j
__device__ float        g_topv[MG*MG];
__device__ int          g_topi[MG*MG];
__device__ float        g_part[NSUM*NPART];   // [q][block] transposed
__device__ int          g_ctrb[NB];      // per-image topk completion tickets (zeroed by k_pred)
__device__ int          g_ctr2;          // loss completion ticket (reset by consumer)

// ---------------- helpers ----------------
__device__ __forceinline__ void giou_pair(
    float px1, float py1, float px2, float py2,
    float gx1, float gy1, float gx2, float gy2,
    float& iou, float& gou)
{
    float iw = fminf(px2, gx2) - fmaxf(px1, gx1); iw = fmaxf(iw, 0.f);
    float ih = fminf(py2, gy2) - fmaxf(py1, gy1); ih = fmaxf(ih, 0.f);
    float inter = iw * ih;
    float ap = (px2 - px1) * (py2 - py1);
    float ag = (gx2 - gx1) * (gy2 - gy1);
    float un = ap + ag - inter;
    iou = __fdividef(inter, un + 1e-16f);
    float cw = fmaxf(px2, gx2) - fminf(px1, gx1);
    float ch = fmaxf(py2, gy2) - fminf(py1, gy1);
    float ac = cw * ch;
    gou = iou - __fdividef(ac - un, ac + 1e-16f);
}

// ---------------- 1. pred transform (+ scratch init) ----------------
__global__ void k_pred(const float* __restrict__ out)
{
    int t = blockIdx.x * blockDim.x + threadIdx.x;       // < NTOT
    int x = t & (GS - 1);
    int y = (t >> 7) & (GS - 1);
    int a = (t / (GS * GS)) % NA;
    int b = t / NPRED;
    const float* base = out + (((size_t)b * NC + a * 5) * GS + y) * GS + x;
    float p0 = base[0];
    float p1 = base[GS * GS];
    float p2 = base[2 * GS * GS];
    float p3 = base[3 * GS * GS];
    float p4 = base[4 * GS * GS];
    float xs = (tanhf(p0) + 0.5f + (float)x) / (float)GS;
    float ys = (tanhf(p1) + 0.5f + (float)y) / (float)GS;
    float ws = expf(-p2 * p2);
    float hs = expf(-p3 * p3);
    float c  = 1.f / (1.f + expf(-p4));
    float cc = fminf(fmaxf(c, 1e-7f), 1.f - 1e-7f);
    g_box [t] = make_float4(xs, ys, ws, hs);
    g_conf[t] = cc;
    g_mt  [t] = 0u;
    if (t < NB) g_ctrb[t] = 0;
}

// ---------------- 2. per-gt top-m lists; last block per image runs its matcher ----------------
__global__ void k_topk(const float* __restrict__ gts)
{
    extern __shared__ float dyn[];
    float* row  = dyn;                          // [NPRED]
    float* segv = dyn + NPRED;                  // [1024]
    int*   segi = (int*)(dyn + NPRED + 1024);   // [1024]
    __shared__ float swv[32];
    __shared__ int   swi[32];
    __shared__ int   bbi;
    __shared__ int   smm;
    __shared__ int   slast;

    int j = blockIdx.x;
    int tid = threadIdx.x;              // 1024
    int b = (int)__ldg(&gts[j * 5]);

    if (tid == 0) {
        int m = 0;
        for (int i = 0; i < MG; i++)
            if ((int)__ldg(&gts[i * 5]) == b) m++;
        smm = m;
    }

    float cx = __ldg(&gts[j * 5 + 1]), cy = __ldg(&gts[j * 5 + 2]);
    float w  = __ldg(&gts[j * 5 + 3]), h  = __ldg(&gts[j * 5 + 4]);
    float gx1 = cx - w * 0.5f, gx2 = cx + w * 0.5f;
    float gy1 = cy - h * 0.5f, gy2 = cy + h * 0.5f;
    const float4* bx = &g_box[(size_t)b * NPRED];

    // initial pass: giou, fill smem row, per-thread segment max
    float bv = -1e30f; int bi = NPRED;
#pragma unroll 8
    for (int k = 0; k < SEGK; k++) {
        int p = tid + k * 1024;
        float4 B = __ldg(&bx[p]);
        float px1 = B.x - B.z * 0.5f, px2 = B.x + B.z * 0.5f;
        float py1 = B.y - B.w * 0.5f, py2 = B.y + B.w * 0.5f;
        float iou, gou;
        giou_pair(px1, py1, px2, py2, gx1, gy1, gx2, gy2, iou, gou);
        row[p] = gou;
        if (gou > bv) { bv = gou; bi = p; }      // ascending p keeps min idx on ties
    }
    segv[tid] = bv; segi[tid] = bi;
    unsigned long long pk = 0ull;                // picked bits within my segment
    __syncthreads();
    int m = smm;

    for (int r = 0; r < m; r++) {
        // block argmax over 1024 segment maxima (min-global-index tie-break)
        float v = segv[tid]; int i = segi[tid];
#pragma unroll
        for (int o = 16; o > 0; o >>= 1) {
            float ov = __shfl_down_sync(0xffffffffu, v, o);
            int   oi = __shfl_down_sync(0xffffffffu, i, o);
            if (ov > v || (ov == v && oi < i)) { v = ov; i = oi; }
        }
        if ((tid & 31) == 0) { swv[tid >> 5] = v; swi[tid >> 5] = i; }
        __syncthreads();
        if (tid < 32) {
            v = swv[tid]; i = swi[tid];
#pragma unroll
            for (int o = 16; o > 0; o >>= 1) {
                float ov = __shfl_down_sync(0xffffffffu, v, o);
                int   oi = __shfl_down_sync(0xffffffffu, i, o);
                if (ov > v || (ov == v && oi < i)) { v = ov; i = oi; }
            }
            if (tid == 0) {
                bbi = i;
                g_topv[j * MG + r] = v;
                g_topi[j * MG + r] = i;
            }
        }
        __syncthreads();
        int wi = bbi;
        if (tid == (wi & 1023)) {
            pk |= 1ull << (wi >> 10);
            float nv = -1e30f; int ni = NPRED;
#pragma unroll
            for (int k = 0; k < SEGK; k++) {
                if ((pk >> k) & 1ull) continue;
                int p = tid + k * 1024;
                float vv = row[p];
                if (vv > nv) { nv = vv; ni = p; }
            }
            segv[tid] = nv; segi[tid] = ni;
        }
        // no barrier: only the rescanner's own segv entry changed and only
        // that thread reads it next round.
    }

    // ---- per-image ticket: last finishing gt-block of image b runs its matcher ----
    __threadfence();
    if (tid == 0) {
        int done = atomicAdd(&g_ctrb[b], 1);
        slast = (done == m - 1);
    }
    __syncthreads();
    if (!slast) return;
    __threadfence();                             // acquire sibling blocks' lists

    // stage all top lists into smem (only image-b rows are consumed; those are complete)
    float* stv = dyn;                                        // [MG*MG]
    int*   sti = (int*)(dyn + MG * MG);                      // [MG*MG]
    unsigned int* mk = (unsigned int*)(dyn + 2 * MG * MG);   // [MASKW]
    for (int i = tid; i < MG * MG; i += 1024) { stv[i] = g_topv[i]; sti[i] = g_topi[i]; }
    for (int i = tid; i < MASKW; i += 1024) mk[i] = 0u;
    __syncthreads();
    if (tid != 0) return;

    // serial greedy matcher for image b (exact reference emulation)
    int jl[MG]; int mc = 0;
    for (int j2 = 0; j2 < MG; j2++)
        if ((int)__ldg(&gts[j2 * 5]) == b) jl[mc++] = j2;
    int mm = mc;                                 // == m
    bool sel[MG];
    for (int i = 0; i < mc; i++) sel[i] = false;
    float valj[MG]; int pdj[MG]; int act[MG];

    while (true) {
        int ma = 0;
        for (int i = 0; i < mc; i++) if (!sel[i]) act[ma++] = i;
        if (ma == 0) break;
        // current best unmatched pred per active gt (first unpicked entry of top list)
        for (int ii = 0; ii < ma; ii++) {
            int j2 = jl[act[ii]];
            valj[ii] = stv[j2 * MG + mm - 1];
            pdj[ii]  = sti[j2 * MG + mm - 1];
            for (int r = 0; r < mm; r++) {
                int p = sti[j2 * MG + r];
                if (!((mk[p >> 5] >> (p & 31)) & 1u)) {
                    valj[ii] = stv[j2 * MG + r];
                    pdj[ii] = p;
                    break;
                }
            }
        }
        // conflict resolution: per contended pred, max val wins (first gt index on ties)
        for (int ii = 0; ii < ma; ii++) {
            int p = pdj[ii];
            bool first = true;
            for (int k = 0; k < ii; k++) if (pdj[k] == p) { first = false; break; }
            if (!first) continue;
            float mx = valj[ii];
            for (int k = ii + 1; k < ma; k++)
                if (pdj[k] == p && valj[k] > mx) mx = valj[k];
            int win = ii;
            for (int k = ii; k < ma; k++)
                if (pdj[k] == p && valj[k] >= mx) { win = k; break; }
            sel[act[win]] = true;
            mk[p >> 5] |= 1u << (p & 31);
            g_mt[(size_t)b * NPRED + p] = 0x80000000u | (unsigned int)jl[act[win]];
        }
    }
}

// ---------------- 3. loss: 256 threads x 4 preds, mc-loop default + last-block fold ----------------
__global__ void k_loss(const float* __restrict__ gts, float* __restrict__ outv)
{
    __shared__ float sgt[MG * 5];          // raw gts
    __shared__ float slw[MG], slh[MG];     // per-gt log(w), log(h)
    __shared__ float cx1[MG], cy1[MG], cx2[MG], cy2[MG];  // compacted corners
    __shared__ int   cj[MG];
    __shared__ int   smc;
    __shared__ int   slast;
    __shared__ float red[8 * NSUM];
    int tid = threadIdx.x;                 // 256
    int b = blockIdx.x / (NPRED / LOSS_CHUNK);   // 48 blocks per image
    for (int i = tid; i < MG * 5; i += 256) sgt[i] = gts[i];
    __syncthreads();
    if (tid < MG) {
        slw[tid] = logf(sgt[tid * 5 + 3]);
        slh[tid] = logf(sgt[tid * 5 + 4]);
    }
    if (tid == 0) {
        int mc = 0;
        for (int j = 0; j < MG; j++) {
            if ((int)sgt[j * 5] != b) continue;
            float gcx = sgt[j * 5 + 1], gcy = sgt[j * 5 + 2];
            float gw  = sgt[j * 5 + 3], gh  = sgt[j * 5 + 4];
            cx1[mc] = gcx - gw * 0.5f; cx2[mc] = gcx + gw * 0.5f;
            cy1[mc] = gcy - gh * 0.5f; cy2[mc] = gcy + gh * 0.5f;
            cj[mc] = j;
            mc++;
        }
        smc = mc;
    }
    __syncthreads();
    int mc = smc;

    float s[NSUM];
#pragma unroll
    for (int q = 0; q < NSUM; q++) s[q] = 0.f;

    int base = blockIdx.x * LOSS_CHUNK;
#pragma unroll
    for (int it = 0; it < LOSS_CHUNK / 256; it++) {
        int t = base + it * 256 + tid;
        float4 B = __ldg(&g_box[t]);
        unsigned int mt = __ldg(&g_mt[t]);
        float cc = __ldg(&g_conf[t]);

        bool tp = (mt & 0x80000000u) != 0u;
        float tpf = tp ? 1.f : 0.f;
        int pi = 0;
        float iou = 0.f, gou = 0.f;

        float px1 = B.x - B.z * 0.5f, px2 = B.x + B.z * 0.5f;
        float py1 = B.y - B.w * 0.5f, py2 = B.y + B.w * 0.5f;

        if (tp) {
            pi = (int)(mt & 0x7FFFFFFFu);
            float tx = sgt[pi * 5 + 1], ty = sgt[pi * 5 + 2];
            float tw = sgt[pi * 5 + 3], th = sgt[pi * 5 + 4];
            giou_pair(px1, py1, px2, py2,
                      tx - tw * 0.5f, ty - th * 0.5f,
                      tx + tw * 0.5f, ty + th * 0.5f, iou, gou);
        } else if (mc > 0) {
            // default: best gt of this image by giou (ascending -> first-index tie-break)
            float best = -1e30f; int bi = 0; float biou = 0.f;
            for (int k = 0; k < mc; k++) {
                float ji, jg;
                giou_pair(px1, py1, px2, py2, cx1[k], cy1[k], cx2[k], cy2[k], ji, jg);
                if (jg > best) { best = jg; bi = k; biou = ji; }
            }
            iou = biou; gou = best;
            pi = cj[bi];
        }
        // mc==0: iou=gou=0, pi=0 (matches reference)

        float tx = sgt[pi * 5 + 1], ty = sgt[pi * 5 + 2];
        float lwgt = slw[pi], lhgt = slh[pi];

        bool thr = iou > 0.5f;
        float igf = ((!thr) || tp) ? 1.f : 0.f;
        float bce = tp ? -logf(cc) : -log1pf(-cc);

        s[0] += tpf;
        float dx = B.x - tx, dy = B.y - ty;
        s[1] += (dx * dx + dy * dy) * tpf;
        float dw = logf(B.z) - lwgt, dh = logf(B.w) - lhgt;
        s[2] += (dw * dw + dh * dh) * tpf;
        s[3] += gou * tpf;
        s[4] += iou * tpf;
        s[5] += igf;
        s[6] += bce * igf;
        s[7] += cc * tpf;
        s[8] += cc * cc * igf;
    }

#pragma unroll
    for (int o = 16; o > 0; o >>= 1) {
#pragma unroll
        for (int q = 0; q < NSUM; q++)
            s[q] += __shfl_down_sync(0xffffffffu, s[q], o);
    }
    if ((tid & 31) == 0) {
#pragma unroll
        for (int q = 0; q < NSUM; q++) red[(tid >> 5) * NSUM + q] = s[q];
    }
    __syncthreads();
    if (tid < NSUM) {
        float acc = 0.f;
        for (int w = 0; w < 8; w++) acc += red[w * NSUM + tid];
        g_part[tid * NPART + blockIdx.x] = acc;     // transposed: contiguous per q
    }

    // ---- completion ticket: last block folds and writes the output ----
    __threadfence();
    __syncthreads();
    if (tid == 0) {
        int done = atomicAdd(&g_ctr2, 1);
        slast = (done == NPART - 1);
        if (slast) g_ctr2 = 0;              // reset for next replay
    }
    __syncthreads();
    if (!slast) return;
    __threadfence();

    // parallel fold: 16 threads per sum, width-16 shuffle.
    // ALL threads execute the shuffle (a=0 for out-of-range lanes) — guards
    // only on accumulation and the final store, so no intra-warp divergence.
    __shared__ double S[NSUM];
    {
        int q = tid >> 4;                  // 0..15 across 256 threads
        int sub = tid & 15;
        double a = 0.0;
        if (q < NSUM) {
            const float* p = &g_part[q * NPART];
            for (int i = sub; i < NPART; i += 16) a += (double)p[i];
        }
#pragma unroll
        for (int o = 8; o > 0; o >>= 1)
            a += __shfl_down_sync(0xffffffffu, a, o, 16);
        if (q < NSUM && sub == 0) S[q] = a;
    }
    __syncthreads();
    if (tid == 0) {
        float s0 = (float)S[0], s1 = (float)S[1], s2 = (float)S[2];
        float s3 = (float)S[3], s4 = (float)S[4], s5 = (float)S[5];
        float s6 = (float)S[6], s7 = (float)S[7], s8 = (float)S[8];
        float cnt = fmaxf(s0, 1.f);
        float lxy  = s1 / cnt;
        float lwh  = s2 / cnt;
        float lgou = 1.f - s3 / cnt;
        float liou = 1.f - s4 / cnt;
        float icnt = fmaxf(s5, 1.f);
        float lbce = s6 / icnt;
        float dice = 1.f - (2.f * s7 + 1.f) / (s8 + s0 + 1.f);
        float lconf = dice + lbce;
        float tot = lconf + 2.f * lgou + lwh + lxy;
        outv[0] = lxy; outv[1] = lwh; outv[2] = lconf;
        outv[3] = liou; outv[4] = lgou; outv[5] = tot;
    }
}

// ---------------- launch ----------------
extern "C" void kernel_launch(void* const* d_in, const int* in_sizes, int n_in,
                              void* d_out, int out_size)
{
    const float* out = (const float*)d_in[0];   // [8,15,128,128]
    const float* gts = (const float*)d_in[1];   // [64,5]
    float* res = (float*)d_out;                 // [6]

    static int smem_set = 0;
    const int TOPK_SMEM = (NPRED + 1024 + 1024) * 4 + 64;   // ~204.9 KB
    if (!smem_set) {
        cudaFuncSetAttribute(k_topk, cudaFuncAttributeMaxDynamicSharedMemorySize, TOPK_SMEM);
        smem_set = 1;
    }

    k_pred <<<NTOT / 512, 512>>>(out);
    k_topk <<<MG, 1024, TOPK_SMEM>>>(gts);
    k_loss <<<NPART, 256>>>(gts, res);
}